// round 1
// baseline (speedup 1.0000x reference)
#include <cuda_runtime.h>
#include <cstdint>

// Static scratch (device globals — no allocation anywhere).
// Sized for B*N*D = 6.4M edges, B*N = 400K nodes, with margin.
#define MAXE 6800000
#define MAXN 430000

__device__ float g_w[MAXE];   // softmax weights, original [b,v,d] layout (for epilogue)
__device__ int2  g_p[MAXE];   // packed edges, layout [d][node]: .x = flat src node, .y = f32 bits of W_in
__device__ float g_xa[MAXN];  // x double buffer
__device__ float g_xb[MAXN];

// ---------------------------------------------------------------------------
// K1: masked softmax over the D neighbor slots of each node (thread per node).
// Padded slots (adj == num_nodes) get -1e7 => exp underflows to exactly 0.
// Three passes re-reading globals (L1 hits) to avoid local-memory arrays for
// dynamic D.
// ---------------------------------------------------------------------------
__global__ void k_softmax(const float* __restrict__ fp, const int* __restrict__ adj,
                          const int* __restrict__ num_nodes, int BN, int D) {
    int t = blockIdx.x * blockDim.x + threadIdx.x;
    if (t >= BN) return;
    const int N = __ldg(num_nodes);
    const float* f = fp + (size_t)t * D;
    const int*   a = adj + (size_t)t * D;

    float m = -3.402823466e38f;
    for (int d = 0; d < D; ++d) {
        float v = __ldg(f + d);
        if (__ldg(a + d) == N) v -= 1e7f;
        m = fmaxf(m, v);
    }
    float s = 0.f;
    for (int d = 0; d < D; ++d) {
        float v = __ldg(f + d);
        if (__ldg(a + d) == N) v -= 1e7f;
        s += __expf(v - m);
    }
    float inv = 1.f / s;
    for (int d = 0; d < D; ++d) {
        float v = __ldg(f + d);
        if (__ldg(a + d) == N) v -= 1e7f;
        g_w[(size_t)t * D + d] = __expf(v - m) * inv;
    }
}

// ---------------------------------------------------------------------------
// K2: gather in-edge weights once. For edge e (node t = e/D, slot d = e%D),
// in_indices gives (fb, fs, fslot) with flow[fb,fs,fslot] = W_in * x[fb,fs].
// Store {flat_src, W_in} in SoA-by-slot layout [d][t] so the iteration kernel
// reads fully coalesced int2 streams.
// ---------------------------------------------------------------------------
__global__ void k_gather(const int* __restrict__ ii, const int* __restrict__ num_nodes,
                         int E, int BN, int D) {
    int e = blockIdx.x * blockDim.x + threadIdx.x;
    if (e >= E) return;
    const int N = __ldg(num_nodes);
    int fb = __ldg(ii + 3 * (size_t)e + 0);
    int fs = __ldg(ii + 3 * (size_t)e + 1);
    int fl = __ldg(ii + 3 * (size_t)e + 2);
    int srcflat = fb * N + fs;                     // flat node index of the source
    float w = g_w[(size_t)srcflat * D + fl];       // padded slots => exactly 0
    int t = e / D;
    int d = e - t * D;
    g_p[(size_t)d * BN + t] = make_int2(srcflat, __float_as_int(w));
}

// ---------------------------------------------------------------------------
// K3: one fixed-point iteration. x_new[t] = relu(sum_d w*x_old[src] - demand[t]).
// Specialized compile-time D for full unroll (16 independent load pairs -> MLP).
// ---------------------------------------------------------------------------
template <int D>
__global__ void __launch_bounds__(256) k_iter(const float* __restrict__ dem,
                                              const float* __restrict__ xo,
                                              float* __restrict__ xn, int BN) {
    int t = blockIdx.x * blockDim.x + threadIdx.x;
    if (t >= BN) return;
    float acc = 0.f;
#pragma unroll
    for (int d = 0; d < D; ++d) {
        int2 p = __ldg(&g_p[(size_t)d * BN + t]);
        acc = fmaf(__int_as_float(p.y), __ldg(xo + p.x), acc);
    }
    xn[t] = fmaxf(acc - __ldg(dem + t), 0.f);
}

__global__ void __launch_bounds__(256) k_iter_gen(const float* __restrict__ dem,
                                                  const float* __restrict__ xo,
                                                  float* __restrict__ xn, int BN, int D) {
    int t = blockIdx.x * blockDim.x + threadIdx.x;
    if (t >= BN) return;
    float acc = 0.f;
    for (int d = 0; d < D; ++d) {
        int2 p = __ldg(&g_p[(size_t)d * BN + t]);
        acc = fmaf(__int_as_float(p.y), __ldg(xo + p.x), acc);
    }
    xn[t] = fmaxf(acc - __ldg(dem + t), 0.f);
}

// ---------------------------------------------------------------------------
// K4: epilogue. flow[b,v,d] = weights[b,v,d] * x_final[b,v]
// ---------------------------------------------------------------------------
__global__ void k_final(float* __restrict__ out, const float* __restrict__ x,
                        int E, unsigned D) {
    int e = blockIdx.x * blockDim.x + threadIdx.x;
    if (e >= E) return;
    out[e] = g_w[e] * __ldg(x + (unsigned)e / D);
}

extern "C" void kernel_launch(void* const* d_in, const int* in_sizes, int n_in,
                              void* d_out, int out_size) {
    const float* fp  = (const float*)d_in[0];   // flow_proportions [B,N,D]
    const float* dem = (const float*)d_in[1];   // demands [B,N,1]
    const int*   adj = (const int*)d_in[2];     // adj_lst [B,N,D]
    const int*   ii  = (const int*)d_in[3];     // in_indices [B,N,D,3]
    const int*   nn  = (const int*)d_in[4];     // num_nodes scalar

    const int E  = in_sizes[0];      // B*N*D
    const int BN = in_sizes[1];      // B*N
    const int D  = E / BN;

    void *pxa = nullptr, *pxb = nullptr;
    cudaGetSymbolAddress(&pxa, g_xa);
    cudaGetSymbolAddress(&pxb, g_xb);
    float* xa = (float*)pxa;
    float* xb = (float*)pxb;

    const int BT = 256;
    const int gN = (BN + BT - 1) / BT;
    const int gE = (E + BT - 1) / BT;

    k_softmax<<<gN, BT>>>(fp, adj, nn, BN, D);
    k_gather<<<gE, BT>>>(ii, nn, E, BN, D);
    cudaMemsetAsync(xa, 0, (size_t)BN * sizeof(float), 0);

    for (int i = 0; i < 32; ++i) {
        const float* xo = (i & 1) ? xb : xa;
        float*       xn = (i & 1) ? xa : xb;
        if (D == 16)
            k_iter<16><<<gN, BT>>>(dem, xo, xn, BN);
        else
            k_iter_gen<<<gN, BT>>>(dem, xo, xn, BN, D);
    }
    // 32 iterations (even) => final x lives in xa
    k_final<<<gE, BT>>>((float*)d_out, xa, E, (unsigned)D);
}